// round 6
// baseline (speedup 1.0000x reference)
#include <cuda_runtime.h>
#include <cuda_bf16.h>

// CasamentoMult on GB300 — bandwidth-targeted: double-buffered loads (8
// outstanding LDG.128/warp) + shuffle for the +8 straggler element.
// sigma = 1/sqrt(2*pi) => log_sqrt_pi == 0; pair term = exp(-pi*diff^2)
//   = 2^(C2*diff^2), C2 = -pi*log2(e).  Collapsed form:
//  total = NE + sum_k [ 0.5*(e(y1-y0)+e(d1-d0)-e(d1-y0)-e(d0-y1)) - e(d0-y0) ]
//             + 0.5*e(d[0]-y[0]) - 0.5*e(d[NE]-y[NE]),   NE = N-2.

#define NBLK 1184          // 148 SMs * 8
#define NTHR 256

__device__ float    g_partials[NBLK];
__device__ unsigned g_ticket = 0;

__device__ __forceinline__ float gex(float x) {
    // 2^(C2*x*x) == exp(-pi*x*x); ex2.approx flushes very negative args to 0.
    float a = (x * -4.532360141827194f) * x;   // C2 = -pi * log2(e)
    float r;
    asm("ex2.approx.f32 %0, %1;" : "=f"(r) : "f"(a));
    return r;
}

__device__ __forceinline__ void term(float& acc, float d0, float d1,
                                     float y0, float y1) {
    float gy = gex(y1 - y0);
    float gd = gex(d1 - d0);
    float c1 = gex(d1 - y0);
    float c2 = gex(d0 - y1);
    float s  = gex(d0 - y0);
    acc = fmaf((gy + gd) - (c1 + c2), 0.5f, acc) - s;
}

__global__ void __launch_bounds__(NTHR)
casa_fused(const float* __restrict__ d, const float* __restrict__ y,
           int NE, int ngroups, float* __restrict__ out) {
    float a0 = 0.f, a1 = 0.f, a2 = 0.f, a3 = 0.f;
    const int stride = gridDim.x * blockDim.x;
    const int lane   = threadIdx.x & 31;

    int  g    = blockIdx.x * blockDim.x + threadIdx.x;
    bool act  = g < ngroups;
    const int itmax = (ngroups + stride - 1) / stride;   // uniform per warp

    int base = act ? (g << 3) : 0;
    float4 dA = *reinterpret_cast<const float4*>(d + base);
    float4 dB = *reinterpret_cast<const float4*>(d + base + 4);
    float4 yA = *reinterpret_cast<const float4*>(y + base);
    float4 yB = *reinterpret_cast<const float4*>(y + base + 4);

    for (int it = 0; it < itmax; it++) {
        // ---- prefetch next group (always issued; dummy base 0 when done) ----
        const int  gn    = g + stride;
        const bool actn  = gn < ngroups;
        const int  basen = actn ? (gn << 3) : 0;
        const float4 dAn = *reinterpret_cast<const float4*>(d + basen);
        const float4 dBn = *reinterpret_cast<const float4*>(d + basen + 4);
        const float4 yAn = *reinterpret_cast<const float4*>(y + basen);
        const float4 yBn = *reinterpret_cast<const float4*>(y + basen + 4);

        // ---- +8 element via neighbor lane (same iteration, group g+1) ----
        float d8 = __shfl_down_sync(0xffffffffu, dA.x, 1);
        float y8 = __shfl_down_sync(0xffffffffu, yA.x, 1);
        if (act && (lane == 31 || g + 1 >= ngroups)) {
            d8 = __ldg(d + (g << 3) + 8);
            y8 = __ldg(y + (g << 3) + 8);
        }

        if (act) {
            term(a0, dA.x, dA.y, yA.x, yA.y);
            term(a1, dA.y, dA.z, yA.y, yA.z);
            term(a2, dA.z, dA.w, yA.z, yA.w);
            term(a3, dA.w, dB.x, yA.w, yB.x);
            term(a0, dB.x, dB.y, yB.x, yB.y);
            term(a1, dB.y, dB.z, yB.y, yB.z);
            term(a2, dB.z, dB.w, yB.z, yB.w);
            term(a3, dB.w, d8,   yB.w, y8);
        }

        dA = dAn; dB = dBn; yA = yAn; yB = yBn;
        g = gn; act = actn;
    }

    float acc = (a0 + a1) + (a2 + a3);

    // block reduce (float)
    #pragma unroll
    for (int o = 16; o; o >>= 1) acc += __shfl_down_sync(0xffffffffu, acc, o);

    __shared__ float sh[NTHR / 32];
    __shared__ bool  s_last;
    const int w = threadIdx.x >> 5;
    if (lane == 0) sh[w] = acc;
    __syncthreads();
    if (threadIdx.x == 0) {
        float v = 0.f;
        #pragma unroll
        for (int i = 0; i < NTHR / 32; i++) v += sh[i];
        g_partials[blockIdx.x] = v;
        __threadfence();
        unsigned t = atomicAdd(&g_ticket, 1u);
        s_last = (t == (unsigned)gridDim.x - 1u);
    }
    __syncthreads();
    if (!s_last) return;

    // ---- last block: deterministic double-precision finish ----
    const int tid = threadIdx.x;
    double v = 0.0;
    for (int i = tid; i < NBLK; i += NTHR)       // fixed-order per thread
        v += (double)g_partials[i];

    if (tid == 0) {
        for (int k = 8 * ngroups; k < NE; k++) { // tail (empty when NE%8==0)
            float t0 = d[k], t1 = d[k + 1], u0 = y[k], u1 = y[k + 1];
            float a = gex(u1 - u0) + gex(t1 - t0) - gex(t1 - u0) - gex(t0 - u1);
            v += 0.5 * (double)a - (double)gex(t0 - u0);
        }
        v += 0.5 * ((double)gex(d[0] - y[0]) - (double)gex(d[NE] - y[NE]));
        v += (double)NE;
    }

    #pragma unroll
    for (int o = 16; o; o >>= 1) v += __shfl_down_sync(0xffffffffu, v, o);

    __shared__ double shd[NTHR / 32];
    if (lane == 0) shd[w] = v;
    __syncthreads();
    if (tid == 0) {
        double t = 0.0;
        #pragma unroll
        for (int i = 0; i < NTHR / 32; i++) t += shd[i];
        out[0] = (float)t;
        g_ticket = 0;                  // reset for next graph replay
    }
}

extern "C" void kernel_launch(void* const* d_in, const int* in_sizes, int n_in,
                              void* d_out, int out_size) {
    const float* d = (const float*)d_in[0];
    const float* y = (const float*)d_in[1];
    float* out = (float*)d_out;

    const int n  = in_sizes[0];
    const int NE = n - 2;               // 4,000,000 for N = 4,000,002
    const int ngroups = NE / 8;         // 8 consecutive k per group

    casa_fused<<<NBLK, NTHR>>>(d, y, NE, ngroups, out);
}

// round 7
// speedup vs baseline: 1.0913x; 1.0913x over previous
#include <cuda_runtime.h>
#include <cuda_bf16.h>

// CasamentoMult on GB300 — MUFU offload v2: 3 exps on MUFU (gy, gd, s),
// 2 exps (c1, c2) on a packed f32x2 polynomial, paired WITHIN one element
// (no cross-element packing).
// sigma = 1/sqrt(2*pi) => log_sqrt_pi == 0; pair term = exp(-pi*diff^2)
//   = 2^(-(SC*diff)^2), SC = sqrt(pi*log2(e)).  Collapsed form:
//  total = NE + sum_k [ 0.5*(gy+gd-c1-c2) - s ]
//             + 0.5*e(d[0]-y[0]) - 0.5*e(d[NE]-y[NE]),   NE = N-2.

#define NBLK 1184          // 148 SMs * 8
#define NTHR 256

__device__ float    g_partials[NBLK];
__device__ unsigned g_ticket = 0;

#define SC     2.1289340388624523f   // sqrt(pi * log2(e))
#define MAGICF 12582912.0f           // 1.5*2^23 (0x4B400000, low 9 bits 0)
#define RMIN   0x4B3FF82             // placeholder guard (real value below)
#undef  RMIN
#define RMIN   0x4B3FFF82            // as_int(MAGICF) - 126

// ---- f32x2 helpers (double containers; FP64 pipe never used) ----
__device__ __forceinline__ double pk2(float lo, float hi) {
    double r; asm("mov.b64 %0, {%1, %2};" : "=d"(r) : "f"(lo), "f"(hi)); return r;
}
__device__ __forceinline__ double fma2(double a, double b, double c) {
    double r; asm("fma.rn.f32x2 %0, %1, %2, %3;" : "=d"(r) : "d"(a), "d"(b), "d"(c)); return r;
}
__device__ __forceinline__ double mul2(double a, double b) {
    double r; asm("mul.rn.f32x2 %0, %1, %2;" : "=d"(r) : "d"(a), "d"(b)); return r;
}
__device__ __forceinline__ float ex2f(float a) {
    float r; asm("ex2.approx.f32 %0, %1;" : "=f"(r) : "f"(a)); return r;
}
__device__ __forceinline__ float gex_raw(float x) {   // exp(-pi*x^2), scalar
    float u = x * SC;
    return ex2f(-u * u);
}

__global__ void __launch_bounds__(NTHR)
casa_fused(const float* __restrict__ d, const float* __restrict__ y,
           int NE, int ngroups, float* __restrict__ out) {
    // packed constants
    const double NEG1 = pk2(-1.f, -1.f);
    const double MG2  = pk2(MAGICF, MAGICF);
    const double K4   = pk2(0.0096181291f, 0.0096181291f);
    const double K3   = pk2(0.0555041087f, 0.0555041087f);
    const double K2   = pk2(0.2402265069f, 0.2402265069f);
    const double K1   = pk2(0.6931471806f, 0.6931471806f);
    const double K0   = pk2(1.0f, 1.0f);

    float accP = 0.f;                 // gy + gd           (weight +0.5)
    float accS = 0.f;                 // s                 (weight -1)
    float accCa = 0.f, accCb = 0.f;   // c1, c2 poly sums  (weight -0.5)
    const int stride = gridDim.x * blockDim.x;

    for (int g = blockIdx.x * blockDim.x + threadIdx.x; g < ngroups; g += stride) {
        const int base = g << 3;                   // 8 elements per group
        const float4 dA = *reinterpret_cast<const float4*>(d + base);
        const float4 dB = *reinterpret_cast<const float4*>(d + base + 4);
        const float4 yA = *reinterpret_cast<const float4*>(y + base);
        const float4 yB = *reinterpret_cast<const float4*>(y + base + 4);
        const float d8r = __ldg(d + base + 8);
        const float y8r = __ldg(y + base + 8);

        float D[9], Y[9];
        D[0]=dA.x*SC; D[1]=dA.y*SC; D[2]=dA.z*SC; D[3]=dA.w*SC;
        D[4]=dB.x*SC; D[5]=dB.y*SC; D[6]=dB.z*SC; D[7]=dB.w*SC; D[8]=d8r*SC;
        Y[0]=yA.x*SC; Y[1]=yA.y*SC; Y[2]=yA.z*SC; Y[3]=yA.w*SC;
        Y[4]=yB.x*SC; Y[5]=yB.y*SC; Y[6]=yB.z*SC; Y[7]=yB.w*SC; Y[8]=y8r*SC;

        #pragma unroll
        for (int j = 0; j < 8; j++) {
            // ---- MUFU part: gy, gd, s ----
            float uy = Y[j + 1] - Y[j];
            float ud = D[j + 1] - D[j];
            float us = D[j] - Y[j];
            float gy = ex2f(-uy * uy);
            float gd = ex2f(-ud * ud);
            float s  = ex2f(-us * us);
            accP += gy + gd;
            accS += s;

            // ---- poly part: (c1, c2) = 2^(-(D1-Y0)^2), 2^(-(D0-Y1)^2) ----
            double Dp = pk2(D[j + 1], D[j]);
            double Yp = pk2(Y[j], Y[j + 1]);
            double u  = fma2(Yp, NEG1, Dp);        // (D1-Y0, D0-Y1)
            double v  = mul2(u, u);                // >= 0
            double r  = fma2(v, NEG1, MG2);        // MAGIC - v
            double rv = fma2(r, NEG1, MG2);        // round(v)
            double f  = fma2(v, NEG1, rv);         // round(v) - v  in [-.5,.5]
            double p  = fma2(f, K4, K3);
            p = fma2(p, f, K2);
            p = fma2(p, f, K1);
            p = fma2(p, f, K0);                    // 2^f
            int r0 = __double2loint(r), r1 = __double2hiint(r);
            int p0 = __double2loint(p), p1 = __double2hiint(p);
            r0 = max(r0, (int)RMIN);               // clamp: v>126 -> ~0
            r1 = max(r1, (int)RMIN);
            // bits = bits(2^f) + (r - MAGICBITS)<<23 ; MAGICBITS<<23 == 0 mod 2^32
            accCa += __uint_as_float((unsigned)r0 * 8388608u + (unsigned)p0);
            accCb += __uint_as_float((unsigned)r1 * 8388608u + (unsigned)p1);
        }
    }

    // total = 0.5*(P - C) - S
    float acc = fmaf(accP - (accCa + accCb), 0.5f, -accS);

    // block reduce (float)
    #pragma unroll
    for (int o = 16; o; o >>= 1) acc += __shfl_down_sync(0xffffffffu, acc, o);

    __shared__ float sh[NTHR / 32];
    __shared__ bool  s_last;
    const int lane = threadIdx.x & 31;
    const int w    = threadIdx.x >> 5;
    if (lane == 0) sh[w] = acc;
    __syncthreads();
    if (threadIdx.x == 0) {
        float v = 0.f;
        #pragma unroll
        for (int i = 0; i < NTHR / 32; i++) v += sh[i];
        g_partials[blockIdx.x] = v;
        __threadfence();
        unsigned t = atomicAdd(&g_ticket, 1u);
        s_last = (t == (unsigned)gridDim.x - 1u);
    }
    __syncthreads();
    if (!s_last) return;

    // ---- last block: deterministic double-precision finish ----
    const int tid = threadIdx.x;
    double v = 0.0;
    for (int i = tid; i < NBLK; i += NTHR)       // fixed-order per thread
        v += (double)g_partials[i];

    if (tid == 0) {
        for (int k = 8 * ngroups; k < NE; k++) { // tail (empty when NE%8==0)
            float t0 = d[k], t1 = d[k + 1], u0 = y[k], u1 = y[k + 1];
            float a = gex_raw(u1 - u0) + gex_raw(t1 - t0)
                    - gex_raw(t1 - u0) - gex_raw(t0 - u1);
            v += 0.5 * (double)a - (double)gex_raw(t0 - u0);
        }
        v += 0.5 * ((double)gex_raw(d[0] - y[0]) - (double)gex_raw(d[NE] - y[NE]));
        v += (double)NE;
    }

    #pragma unroll
    for (int o = 16; o; o >>= 1) v += __shfl_down_sync(0xffffffffu, v, o);

    __shared__ double shd[NTHR / 32];
    if (lane == 0) shd[w] = v;
    __syncthreads();
    if (tid == 0) {
        double t = 0.0;
        #pragma unroll
        for (int i = 0; i < NTHR / 32; i++) t += shd[i];
        out[0] = (float)t;
        g_ticket = 0;                  // reset for next graph replay
    }
}

extern "C" void kernel_launch(void* const* d_in, const int* in_sizes, int n_in,
                              void* d_out, int out_size) {
    const float* d = (const float*)d_in[0];
    const float* y = (const float*)d_in[1];
    float* out = (float*)d_out;

    const int n  = in_sizes[0];
    const int NE = n - 2;               // 4,000,000 for N = 4,000,002
    const int ngroups = NE / 8;         // 8 consecutive k per group

    casa_fused<<<NBLK, NTHR>>>(d, y, NE, ngroups, out);
}

// round 8
// speedup vs baseline: 1.1078x; 1.0151x over previous
#include <cuda_runtime.h>
#include <cuda_bf16.h>

// CasamentoMult on GB300 — consecutive-pair f32x2 packing: all 5 diff
// categories per element pair are lane-wise packed ops on natural register
// pairs (no cross-lane movs).  sigma = 1/sqrt(2*pi) => log_sqrt_pi == 0;
// pair term = exp(-pi*diff^2) = 2^(-(SC*diff)^2), SC = sqrt(pi*log2(e)).
//  total = NE + sum_k [ 0.5*(gy+gd-c1-c2) - s ]
//             + 0.5*e(d[0]-y[0]) - 0.5*e(d[NE]-y[NE]),   NE = N-2.

#define NBLK 1184          // 148 SMs * 8
#define NTHR 256

__device__ float    g_partials[NBLK];
__device__ unsigned g_ticket = 0;

#define SC 2.1289340388624523f   // sqrt(pi * log2(e))

// ---- f32x2 helpers (double containers; FP64 pipe never used) ----
__device__ __forceinline__ double pk2(float lo, float hi) {
    double r; asm("mov.b64 %0, {%1, %2};" : "=d"(r) : "f"(lo), "f"(hi)); return r;
}
__device__ __forceinline__ float lo2(double v) {
    return __uint_as_float((unsigned)__double2loint(v));
}
__device__ __forceinline__ float hi2(double v) {
    return __uint_as_float((unsigned)__double2hiint(v));
}
__device__ __forceinline__ double sub2(double a, double b) {   // a - b
    double r; asm("sub.rn.f32x2 %0, %1, %2;" : "=d"(r) : "d"(a), "d"(b)); return r;
}
__device__ __forceinline__ double mul2(double a, double b) {
    double r; asm("mul.rn.f32x2 %0, %1, %2;" : "=d"(r) : "d"(a), "d"(b)); return r;
}
__device__ __forceinline__ float ex2f(float a) {
    float r; asm("ex2.approx.f32 %0, %1;" : "=f"(r) : "f"(a)); return r;
}
__device__ __forceinline__ float gex_raw(float x) {   // exp(-pi*x^2), scalar
    float u = x * SC;
    return ex2f(-(u * u));
}

__global__ void __launch_bounds__(NTHR)
casa_fused(const float* __restrict__ d, const float* __restrict__ y,
           int NE, int ngroups, float* __restrict__ out) {
    const double SC2 = pk2(SC, SC);

    float accA0 = 0.f, accA1 = 0.f;   // gy + gd           (weight +0.5)
    float accC0 = 0.f, accC1 = 0.f;   // c1 + c2           (weight -0.5)
    float accS0 = 0.f, accS1 = 0.f;   // s                 (weight -1)
    const int stride = gridDim.x * blockDim.x;

    for (int g = blockIdx.x * blockDim.x + threadIdx.x; g < ngroups; g += stride) {
        const int base = g << 3;                   // 8 elements per group
        const float4 dA = *reinterpret_cast<const float4*>(d + base);
        const float4 dB = *reinterpret_cast<const float4*>(d + base + 4);
        const float4 yA = *reinterpret_cast<const float4*>(y + base);
        const float4 yB = *reinterpret_cast<const float4*>(y + base + 4);
        const float d8 = __ldg(d + base + 8) * SC;
        const float y8 = __ldg(y + base + 8) * SC;

        // even pairs (k, k+1) — direct from the load quads, prescaled packed
        double Dp[4], Yp[4];
        Dp[0] = mul2(pk2(dA.x, dA.y), SC2);
        Dp[1] = mul2(pk2(dA.z, dA.w), SC2);
        Dp[2] = mul2(pk2(dB.x, dB.y), SC2);
        Dp[3] = mul2(pk2(dB.z, dB.w), SC2);
        Yp[0] = mul2(pk2(yA.x, yA.y), SC2);
        Yp[1] = mul2(pk2(yA.z, yA.w), SC2);
        Yp[2] = mul2(pk2(yB.x, yB.y), SC2);
        Yp[3] = mul2(pk2(yB.z, yB.w), SC2);

        #pragma unroll
        for (int p = 0; p < 4; p++) {
            // odd pairs (k+1, k+2)
            const float dn = (p < 3) ? lo2(Dp[p + 1]) : d8;
            const float yn = (p < 3) ? lo2(Yp[p + 1]) : y8;
            const double Dq = pk2(hi2(Dp[p]), dn);
            const double Yq = pk2(hi2(Yp[p]), yn);

            // five packed diff categories, two elements each
            const double qG = sub2(Yq, Yp[p]);     // (gy_k, gy_{k+1})
            const double qD = sub2(Dq, Dp[p]);     // (gd_k, gd_{k+1})
            const double qS = sub2(Dp[p], Yp[p]);  // (s_k,  s_{k+1})
            const double q1 = sub2(Dq, Yp[p]);     // (c1_k, c1_{k+1})
            const double q2 = sub2(Dp[p], Yq);     // (c2_k, c2_{k+1})

            const double vG = mul2(qG, qG);
            const double vD = mul2(qD, qD);
            const double vS = mul2(qS, qS);
            const double v1 = mul2(q1, q1);
            const double v2 = mul2(q2, q2);

            // ex2(-v): negation folds into MUFU input modifier
            accA0 += ex2f(-lo2(vG)) + ex2f(-lo2(vD));
            accA1 += ex2f(-hi2(vG)) + ex2f(-hi2(vD));
            accC0 += ex2f(-lo2(v1)) + ex2f(-lo2(v2));
            accC1 += ex2f(-hi2(v1)) + ex2f(-hi2(v2));
            accS0 += ex2f(-lo2(vS));
            accS1 += ex2f(-hi2(vS));
        }
    }

    // total = 0.5*(A - C) - S
    float acc = fmaf((accA0 + accA1) - (accC0 + accC1), 0.5f,
                     -(accS0 + accS1));

    // block reduce (float)
    #pragma unroll
    for (int o = 16; o; o >>= 1) acc += __shfl_down_sync(0xffffffffu, acc, o);

    __shared__ float sh[NTHR / 32];
    __shared__ bool  s_last;
    const int lane = threadIdx.x & 31;
    const int w    = threadIdx.x >> 5;
    if (lane == 0) sh[w] = acc;
    __syncthreads();
    if (threadIdx.x == 0) {
        float v = 0.f;
        #pragma unroll
        for (int i = 0; i < NTHR / 32; i++) v += sh[i];
        g_partials[blockIdx.x] = v;
        __threadfence();
        unsigned t = atomicAdd(&g_ticket, 1u);
        s_last = (t == (unsigned)gridDim.x - 1u);
    }
    __syncthreads();
    if (!s_last) return;

    // ---- last block: deterministic double-precision finish ----
    const int tid = threadIdx.x;
    double v = 0.0;
    for (int i = tid; i < NBLK; i += NTHR)       // fixed-order per thread
        v += (double)g_partials[i];

    if (tid == 0) {
        for (int k = 8 * ngroups; k < NE; k++) { // tail (empty when NE%8==0)
            float t0 = d[k], t1 = d[k + 1], u0 = y[k], u1 = y[k + 1];
            float a = gex_raw(u1 - u0) + gex_raw(t1 - t0)
                    - gex_raw(t1 - u0) - gex_raw(t0 - u1);
            v += 0.5 * (double)a - (double)gex_raw(t0 - u0);
        }
        v += 0.5 * ((double)gex_raw(d[0] - y[0]) - (double)gex_raw(d[NE] - y[NE]));
        v += (double)NE;
    }

    #pragma unroll
    for (int o = 16; o; o >>= 1) v += __shfl_down_sync(0xffffffffu, v, o);

    __shared__ double shd[NTHR / 32];
    if (lane == 0) shd[w] = v;
    __syncthreads();
    if (tid == 0) {
        double t = 0.0;
        #pragma unroll
        for (int i = 0; i < NTHR / 32; i++) t += shd[i];
        out[0] = (float)t;
        g_ticket = 0;                  // reset for next graph replay
    }
}

extern "C" void kernel_launch(void* const* d_in, const int* in_sizes, int n_in,
                              void* d_out, int out_size) {
    const float* d = (const float*)d_in[0];
    const float* y = (const float*)d_in[1];
    float* out = (float*)d_out;

    const int n  = in_sizes[0];
    const int NE = n - 2;               // 4,000,000 for N = 4,000,002
    const int ngroups = NE / 8;         // 8 consecutive k per group

    casa_fused<<<NBLK, NTHR>>>(d, y, NE, ngroups, out);
}